// round 1
// baseline (speedup 1.0000x reference)
#include <cuda_runtime.h>
#include <cuda_bf16.h>
#include <cstdint>

// RoPE2D encoder: output = [cos_2d (HW x 128) ; sin_2d (HW x 128)], fp32.
// H = W = 512, DIM = 128. Channels [0,64) depend only on x (w-position),
// channels [64,128) only on y. Strategy:
//   kernel 1: build tiny sincos tables (512 KB total) with sincosf.
//   kernel 2: broadcast tables to the 268 MB output with float4 stores.

#define RP_H 512
#define RP_W 512
#define RP_HW (RP_H * RP_W)

// [which(cos=0,sin=1)][pos][channel 0..63]  (channel d uses k = d % 32, duplicated)
__device__ float g_tabx[2][RP_W][64];
__device__ float g_taby[2][RP_H][64];

__global__ void rope2d_build_tables(const float* __restrict__ inv_freq_x,
                                    const float* __restrict__ inv_freq_y) {
    int i = blockIdx.x * blockDim.x + threadIdx.x;   // 0 .. 32767
    if (i >= 2 * 512 * 32) return;
    int table = i >> 14;          // 0 = x-table, 1 = y-table
    int r     = i & 16383;
    int pos   = r >> 5;           // 0..511
    int k     = r & 31;           // 0..31

    float inv = table ? inv_freq_y[k] : inv_freq_x[k];
    float ang = (float)pos * inv;
    float s, c;
    sincosf(ang, &s, &c);

    if (table == 0) {
        g_tabx[0][pos][k]      = c;
        g_tabx[0][pos][k + 32] = c;
        g_tabx[1][pos][k]      = s;
        g_tabx[1][pos][k + 32] = s;
    } else {
        g_taby[0][pos][k]      = c;
        g_taby[0][pos][k + 32] = c;
        g_taby[1][pos][k]      = s;
        g_taby[1][pos][k + 32] = s;
    }
}

// One thread per float4 of the combined output.
// e layout: [which (1 bit)][p (18 bits: y*512 + x)][q (5 bits: float4 chunk of 128-ch row)]
// Total float4 elements = 2 * HW * 32 = 16,777,216.
__global__ void __launch_bounds__(256) rope2d_write(float4* __restrict__ out) {
    unsigned e = blockIdx.x * blockDim.x + threadIdx.x;
    unsigned which = e >> 23;                 // 0 = cos half, 1 = sin half
    unsigned rem   = e & ((1u << 23) - 1u);
    unsigned p     = rem >> 5;                // position index 0..HW-1
    unsigned q     = rem & 31u;               // float4 chunk 0..31 within row
    unsigned y     = p >> 9;                  // 0..511
    unsigned x     = p & 511u;                // 0..511

    const float4* tx = reinterpret_cast<const float4*>(g_tabx[which]); // [512][16]
    const float4* ty = reinterpret_cast<const float4*>(g_taby[which]); // [512][16]

    float4 v = (q < 16u) ? tx[x * 16u + q] : ty[y * 16u + (q - 16u)];
    out[e] = v;
}

extern "C" void kernel_launch(void* const* d_in, const int* in_sizes, int n_in,
                              void* d_out, int out_size) {
    const float* inv_freq_x = (const float*)d_in[1];
    const float* inv_freq_y = (const float*)d_in[2];
    float4* out = (float4*)d_out;

    // Build tables: 2 * 512 * 32 = 32768 threads
    rope2d_build_tables<<<128, 256>>>(inv_freq_x, inv_freq_y);

    // Write output: 16,777,216 float4 -> 65536 blocks of 256 threads
    rope2d_write<<<65536, 256>>>(out);
}

// round 2
// speedup vs baseline: 1.4005x; 1.4005x over previous
#include <cuda_runtime.h>
#include <cuda_bf16.h>
#include <cstdint>

// RoPE2D encoder: output = [cos_2d (HW x 128) ; sin_2d (HW x 128)], fp32.
// H = W = 512, DIM = 128. Channels [0,64) depend only on x, [64,128) only on y.
// kernel 1: tiny sincos tables (512 KB) via sincosf.
// kernel 2: table broadcast, 8 rows per warp for ILP + table-load reuse.

#define RP_H 512
#define RP_W 512
#define RP_HW (RP_H * RP_W)
#define ROWS_PER_WARP 8

// [which(cos=0,sin=1)][pos][channel 0..63]  (channel d uses k = d % 32, duplicated)
__device__ float g_tabx[2][RP_W][64];
__device__ float g_taby[2][RP_H][64];

__global__ void rope2d_build_tables(const float* __restrict__ inv_freq_x,
                                    const float* __restrict__ inv_freq_y) {
    int i = blockIdx.x * blockDim.x + threadIdx.x;   // 0 .. 32767
    if (i >= 2 * 512 * 32) return;
    int table = i >> 14;          // 0 = x-table, 1 = y-table
    int r     = i & 16383;
    int pos   = r >> 5;           // 0..511
    int k     = r & 31;           // 0..31

    float inv = table ? inv_freq_y[k] : inv_freq_x[k];
    float ang = (float)pos * inv;
    float s, c;
    sincosf(ang, &s, &c);

    if (table == 0) {
        g_tabx[0][pos][k]      = c;
        g_tabx[0][pos][k + 32] = c;
        g_tabx[1][pos][k]      = s;
        g_tabx[1][pos][k + 32] = s;
    } else {
        g_taby[0][pos][k]      = c;
        g_taby[0][pos][k + 32] = c;
        g_taby[1][pos][k]      = s;
        g_taby[1][pos][k + 32] = s;
    }
}

// Each warp: fixed `which`, 8 consecutive positions p0..p0+7 (same y, since
// p0 is a multiple of 8 and 8 | 512). Lane = float4 chunk q (0..31) of the
// 128-channel row. q<16 -> x-table (reloaded per row, 8 independent loads);
// q>=16 -> y-table (loaded once, reused 8x). 8 coalesced 512B stores/warp.
__global__ void __launch_bounds__(256) rope2d_write(float4* __restrict__ out) {
    unsigned warp_in_block = threadIdx.x >> 5;
    unsigned q             = threadIdx.x & 31u;
    unsigned gw    = blockIdx.x * 8u + warp_in_block;   // global warp id, 0..65535
    unsigned which = gw >> 15;                          // 0 = cos, 1 = sin
    unsigned rp    = gw & 32767u;
    unsigned p0    = rp * ROWS_PER_WARP;                // base position
    unsigned y     = p0 >> 9;
    unsigned x0    = p0 & 511u;

    const float4* tx = reinterpret_cast<const float4*>(g_tabx[which]); // [512][16]
    const float4* ty = reinterpret_cast<const float4*>(g_taby[which]); // [512][16]

    bool is_x = (q < 16u);
    // y-half lanes: one load, reused for all 8 rows.
    // x-half lanes: 8 independent loads (issued back-to-back below).
    float4 v[ROWS_PER_WARP];
    float4 vy = ty[y * 16u + (q & 15u)];

    #pragma unroll
    for (int i = 0; i < ROWS_PER_WARP; i++) {
        if (is_x) v[i] = tx[(x0 + i) * 16u + q];
        else      v[i] = vy;
    }

    float4* dst = out + (size_t)which * (RP_HW * 32u) + (size_t)p0 * 32u + q;
    #pragma unroll
    for (int i = 0; i < ROWS_PER_WARP; i++) {
        __stcs(dst + (size_t)i * 32u, v[i]);   // streaming store, evict-first
    }
}

extern "C" void kernel_launch(void* const* d_in, const int* in_sizes, int n_in,
                              void* d_out, int out_size) {
    const float* inv_freq_x = (const float*)d_in[1];
    const float* inv_freq_y = (const float*)d_in[2];
    float4* out = (float4*)d_out;

    // Build tables: 2 * 512 * 32 = 32768 threads
    rope2d_build_tables<<<128, 256>>>(inv_freq_x, inv_freq_y);

    // 65536 warps total, 8 warps per block -> 8192 blocks
    rope2d_write<<<8192, 256>>>(out);
}